// round 10
// baseline (speedup 1.0000x reference)
#include <cuda_runtime.h>
#include <math_constants.h>

#define HH 512
#define WW 1024
#define NPIX (HH * WW)      // 524288 = 2^19
#define KNB 15
#define GAMMA_F 0.1f

#define P2_BLOCK 256
#define P2_GRID  (NPIX / P2_BLOCK)   // 2048
#define TILE 5
#define NTILE (KNB / TILE)            // 3

// Packed per-pixel data, 16 bytes: (s, nx, ny, nz).
__device__ float4 g_packed[NPIX];
__device__ float  g_partials[P2_GRID];

__device__ __forceinline__ unsigned smem_u32(const void* p) {
    return (unsigned)__cvta_generic_to_shared(p);
}

// Direction from pixel index (ERP grid), fast intrinsics.
__device__ __forceinline__ void erp_dir(int i, float& dx, float& dy, float& dz) {
    int row = i >> 10;          // W = 1024
    int col = i & 1023;
    float lat = 0.5f * CUDART_PI_F - (row + 0.5f) * (CUDART_PI_F / HH);
    float lon = (col + 0.5f) * (2.0f * CUDART_PI_F / WW) - CUDART_PI_F;
    float sla = __sinf(lat), cla = __cosf(lat);
    float slo = __sinf(lon), clo = __cosf(lon);
    dx = cla * slo;
    dy = sla;
    dz = cla * clo;
}

// ---------------- Pass 1: interleave {s, nx, ny, nz}, x4 unrolled ----------------
__global__ void __launch_bounds__(256) pack_kernel(const float* __restrict__ sig1,
                                                   const float* __restrict__ sig2) {
    int base = blockIdx.x * 1024 + threadIdx.x;   // 512 blocks, 4 pixels/thread
    float s0[4], nx0[4], ny0[4], nz0[4];
#pragma unroll
    for (int q = 0; q < 4; q++) {
        int i = base + q * 256;
        s0[q]  = sig1[i];
        nx0[q] = sig2[i];
        ny0[q] = sig2[NPIX + i];
        nz0[q] = sig2[2 * NPIX + i];
    }
#pragma unroll
    for (int q = 0; q < 4; q++) {
        int i = base + q * 256;
        g_packed[i] = make_float4(s0[q], nx0[q], ny0[q], nz0[q]);
    }
}

// ---------------- Pass 2: cp.async deep-queue gathers ----------------
// Gathers go through cp.async.cg (L1-bypass, no observed outstanding-depth cap)
// into double-buffered smem; each thread consumes only its own slots, so
// per-thread commit/wait groups suffice (no block barriers in the hot loop).
__global__ void __launch_bounds__(P2_BLOCK) loss_kernel(const float* __restrict__ weights,
                                                        const int* __restrict__ nb) {
    __shared__ float4 buf[2][TILE][P2_BLOCK];   // 40 KB static

    int i = blockIdx.x * P2_BLOCK + threadIdx.x;
    int tid = threadIdx.x;

    // Preload all 15 neighbour indices (independent coalesced loads)
    int idx[KNB];
#pragma unroll
    for (int k = 0; k < KNB; k++)
        idx[k] = __ldcs(&nb[k * NPIX + i]) & (NPIX - 1);

    // Prime: issue tile 0 gathers via cp.async (one 16B request per neighbour)
#pragma unroll
    for (int u = 0; u < TILE; u++) {
        unsigned s = smem_u32(&buf[0][u][tid]);
        const float4* g = &g_packed[idx[u]];
        asm volatile("cp.async.cg.shared.global [%0], [%1], 16;\n"
                     :: "r"(s), "l"(g) : "memory");
    }
    asm volatile("cp.async.commit_group;\n" ::: "memory");

    // Own pixel (coalesced 16B load + analytic direction)
    float4 E = __ldg(&g_packed[i]);
    float dix, diy, diz;
    erp_dir(i, dix, diy, diz);
    float nix = E.y, niy = E.z, niz = E.w;
    float pn_i = E.x * (dix * nix + diy * niy + diz * niz);

    float acc1 = 0.0f;   // sum_k (aux1*w)^2
    float acc2 = 0.0f;   // sum_k aux2*w

#pragma unroll
    for (int t = 0; t < NTILE; t++) {
        // Issue next tile's gathers before consuming this one (2 groups in flight)
        if (t + 1 < NTILE) {
#pragma unroll
            for (int u = 0; u < TILE; u++) {
                unsigned s = smem_u32(&buf[(t + 1) & 1][u][tid]);
                const float4* g = &g_packed[idx[(t + 1) * TILE + u]];
                asm volatile("cp.async.cg.shared.global [%0], [%1], 16;\n"
                             :: "r"(s), "l"(g) : "memory");
            }
            asm volatile("cp.async.commit_group;\n" ::: "memory");
            asm volatile("cp.async.wait_group 1;\n" ::: "memory");
        } else {
            asm volatile("cp.async.wait_group 0;\n" ::: "memory");
        }

        // Weights for this tile (coalesced, evict-first)
        float wv[TILE];
#pragma unroll
        for (int u = 0; u < TILE; u++)
            wv[u] = __ldcs(&weights[(t * TILE + u) * NPIX + i]);

        // Consume this tile from smem
#pragma unroll
        for (int u = 0; u < TILE; u++) {
            float4 e = buf[t & 1][u][tid];
            int j = idx[t * TILE + u];

            float djx, djy, djz;
            erp_dir(j, djx, djy, djz);

            float dotpn = e.x * (djx * nix + djy * niy + djz * niz);
            float aux1 = pn_i - dotpn;

            float ddx = nix - e.y;
            float ddy = niy - e.z;
            float ddz = niz - e.w;
            float aux2 = sqrtf(ddx * ddx + ddy * ddy + ddz * ddz);

            float tt = aux1 * wv[u];
            acc1 += tt * tt;
            acc2 += aux2 * wv[u];
        }
    }

    float v = sqrtf(acc1) + GAMMA_F * acc2;

    // Deterministic block tree-reduce (reuse gather smem as scratch)
    float* sm = (float*)&buf[0][0][0];
    __syncthreads();
    sm[tid] = v;
    __syncthreads();
#pragma unroll
    for (int s = P2_BLOCK / 2; s > 0; s >>= 1) {
        if (tid < s) sm[tid] += sm[tid + s];
        __syncthreads();
    }
    if (tid == 0) g_partials[blockIdx.x] = sm[0];
}

// ---------------- Pass 3: deterministic final reduce ----------------
__global__ void __launch_bounds__(1024) finalize_kernel(float* __restrict__ out) {
    __shared__ float sm[1024];
    float v = 0.0f;
#pragma unroll
    for (int idx = threadIdx.x; idx < P2_GRID; idx += 1024)
        v += g_partials[idx];
    sm[threadIdx.x] = v;
    __syncthreads();
#pragma unroll
    for (int s = 512; s > 0; s >>= 1) {
        if (threadIdx.x < s) sm[threadIdx.x] += sm[threadIdx.x + s];
        __syncthreads();
    }
    if (threadIdx.x == 0)
        out[0] = sm[0] * (1.0f / (float)NPIX);   // MULTIPLIER = 1.0
}

extern "C" void kernel_launch(void* const* d_in, const int* in_sizes, int n_in,
                              void* d_out, int out_size) {
    const float* sig1    = (const float*)d_in[0];   // N f32
    const float* sig2    = (const float*)d_in[1];   // 3N f32
    const float* weights = (const float*)d_in[2];   // K*N f32
    const int*   nb      = (const int*)d_in[3];     // K*N int32
    float* out = (float*)d_out;

    pack_kernel<<<NPIX / 1024, 256>>>(sig1, sig2);
    loss_kernel<<<P2_GRID, P2_BLOCK>>>(weights, nb);
    finalize_kernel<<<1, 1024>>>(out);
}